// round 1
// baseline (speedup 1.0000x reference)
#include <cuda_runtime.h>
#include <cuda_bf16.h>
#include <cstdint>

// Problem constants (fixed by the dataset problem)
#define BB     2048
#define TT     256
#define OBS_D  7      // ob(4) + ts(2) + act(1)
#define LDIM   32
#define ODIM   20
#define ADIM   3
#define ROWS   16     // batch rows per CTA
#define NTH    256    // threads per CTA (16 slots x 16 rows)
#define NCTA   (BB / ROWS)

// ---------------------------------------------------------------------------
// Shared memory layout. Every array size is a multiple of 4 floats so float4
// accesses stay 16B-aligned. State arrays padded (stride 33 / 21 / 68 / 132)
// for bank-conflict-free or near-free access across the 16 rows in a warp.
// ---------------------------------------------------------------------------
struct Smem {
    float WxiT[64 * 64];     // [k][j]  k: input idx (h 0-31, c 32-63), j: output
    float Wxi_act[ADIM * 64];// [a][j]  one-hot columns of W_xi
    float bxi[64];
    float Wl1w[ODIM * 64];   // row-major [j][k]
    float bl1v[ODIM];
    float Wl2w[ODIM * ODIM]; // row-major
    float bl2v[ODIM];
    float Wl3T[ODIM * 64];   // [k][j]
    float bl3v[64];
    float WhhT[32 * 128];    // [k][j]
    float h[ROWS * 33];      // LSTM h state (also holds h_in after stage 4)
    float c[ROWS * 33];      // LSTM c state (also holds c_in after stage 4)
    float zp[ROWS * 68];     // zp buffer (stride 68 -> float4-aligned rows)
    float z1[ROWS * 21];
    float z2[ROWS * 21];
    float gate[ROWS * 132];  // 128 gates per row, stride 132
    float ob[ROWS * 8];      // per-step obs fields (7 used)
};

__device__ __forceinline__ float sigf(float x) {
    return __fdividef(1.0f, 1.0f + __expf(-x));
}
__device__ __forceinline__ float tanh_f(float x) {
    // tanh(x) = 2*sigmoid(2x) - 1 ; rel err ~1e-6, well under 1e-3 budget
    return 2.0f * sigf(2.0f * x) - 1.0f;
}

__global__ __launch_bounds__(NTH, 1)
void ppo_rnn_kernel(const float* __restrict__ obs,
                    const float* __restrict__ h0,
                    const float* __restrict__ c0,
                    const float* __restrict__ W1,
                    const float* __restrict__ b1,
                    const float* __restrict__ W_ih,
                    const float* __restrict__ W_hh,
                    const float* __restrict__ b_ih,
                    const float* __restrict__ b_hh,
                    const float* __restrict__ W_xi,
                    const float* __restrict__ b_xi,
                    const float* __restrict__ Wl1,
                    const float* __restrict__ bl1,
                    const float* __restrict__ Wl2,
                    const float* __restrict__ bl2,
                    const float* __restrict__ Wl3,
                    const float* __restrict__ bl3,
                    float* __restrict__ out)
{
    extern __shared__ float smem_raw[];
    Smem* s = reinterpret_cast<Smem*>(smem_raw);

    const int tid  = threadIdx.x;
    const int r    = tid & 15;    // batch row within CTA
    const int slot = tid >> 4;    // work slot 0..15
    const int b0   = blockIdx.x * ROWS;

    // ---- stage weights into smem (transposed where useful) ----
    for (int i = tid; i < 64 * 64; i += NTH) {
        int k = i >> 6, j = i & 63;
        s->WxiT[i] = W_xi[j * 67 + k];
    }
    for (int i = tid; i < ADIM * 64; i += NTH) {
        int a = i >> 6, j = i & 63;
        s->Wxi_act[i] = W_xi[j * 67 + 64 + a];
    }
    for (int i = tid; i < 64; i += NTH) { s->bxi[i] = b_xi[i]; s->bl3v[i] = bl3[i]; }
    for (int i = tid; i < ODIM * 64; i += NTH) s->Wl1w[i] = Wl1[i];
    for (int i = tid; i < ODIM; i += NTH) { s->bl1v[i] = bl1[i]; s->bl2v[i] = bl2[i]; }
    for (int i = tid; i < ODIM * ODIM; i += NTH) s->Wl2w[i] = Wl2[i];
    for (int i = tid; i < ODIM * 64; i += NTH) {
        int k = i >> 6, j = i & 63;
        s->Wl3T[i] = Wl3[j * ODIM + k];
    }
    for (int i = tid; i < 32 * 128; i += NTH) {
        int k = i >> 7, j = i & 127;
        s->WhhT[i] = W_hh[j * 32 + k];
    }
    // ---- initial state ----
    for (int i = tid; i < ROWS * LDIM; i += NTH) {
        int rr = i >> 5, j = i & 31;
        s->h[rr * 33 + j] = h0[(b0 + rr) * LDIM + j];
        s->c[rr * 33 + j] = c0[(b0 + rr) * LDIM + j];
    }

    // ---- fold W1/W_ih: M = W_ih @ W1 (128x4), bvec = W_ih@b1 + b_ih + b_hh ----
    // Each thread owns gate outputs j0..j0+7 (per its slot); kept in registers.
    float Mreg[8][4];
    float bvec[8];
    {
        const int j0 = slot * 8;
        #pragma unroll
        for (int jj = 0; jj < 8; ++jj) {
            const int j = j0 + jj;
            float a0 = 0.f, m0 = 0.f, m1 = 0.f, m2 = 0.f, m3 = 0.f;
            for (int m = 0; m < 64; ++m) {
                float w = W_ih[j * 64 + m];
                a0 += w * b1[m];
                m0 += w * W1[m * 4 + 0];
                m1 += w * W1[m * 4 + 1];
                m2 += w * W1[m * 4 + 2];
                m3 += w * W1[m * 4 + 3];
            }
            bvec[jj]    = a0 + b_ih[j] + b_hh[j];
            Mreg[jj][0] = m0; Mreg[jj][1] = m1; Mreg[jj][2] = m2; Mreg[jj][3] = m3;
        }
    }
    __syncthreads();

    // ---------------------------------------------------------------------
    // Sequential scan over T timesteps
    // ---------------------------------------------------------------------
    for (int t = 0; t < TT; ++t) {
        // S0: load this step's obs fields (7 per row) into smem
        if (slot < OBS_D) {
            s->ob[r * 8 + slot] = obs[((size_t)(b0 + r) * TT + t) * OBS_D + slot];
        }
        __syncthreads();

        const float ts0 = s->ob[r * 8 + 4];
        const float ts1 = s->ob[r * 8 + 5];
        const bool  cond = (ts0 + ts1) != 0.0f;
        const float dt   = ts1 - ts0;
        const int   act  = (int)s->ob[r * 8 + 6];

        // S1: zp = [h;c] @ W_xi[:, :64].T + b_xi + W_xi[:, 64+act]
        float zpr[4];
        {
            const int j0 = slot * 4;
            float4 bx = *(const float4*)&s->bxi[j0];
            float4 wa = *(const float4*)&s->Wxi_act[act * 64 + j0];
            zpr[0] = bx.x + wa.x; zpr[1] = bx.y + wa.y;
            zpr[2] = bx.z + wa.z; zpr[3] = bx.w + wa.w;
            #pragma unroll
            for (int k = 0; k < 32; ++k) {
                float a = s->h[r * 33 + k];
                float4 w = *(const float4*)&s->WxiT[k * 64 + j0];
                zpr[0] += a * w.x; zpr[1] += a * w.y;
                zpr[2] += a * w.z; zpr[3] += a * w.w;
            }
            #pragma unroll
            for (int k = 0; k < 32; ++k) {
                float a = s->c[r * 33 + k];
                float4 w = *(const float4*)&s->WxiT[(32 + k) * 64 + j0];
                zpr[0] += a * w.x; zpr[1] += a * w.y;
                zpr[2] += a * w.z; zpr[3] += a * w.w;
            }
            *(float4*)&s->zp[r * 68 + j0] = make_float4(zpr[0], zpr[1], zpr[2], zpr[3]);
        }
        __syncthreads();

        // S2: z1 = relu(zp @ Wl1.T + bl1)   (20 outputs/row)
        {
            const int  j1   = slot;        // 0..15
            const int  j2   = 16 + slot;   // valid for slot<4
            const bool has2 = (slot < 4);
            float acc1 = s->bl1v[j1];
            float acc2 = has2 ? s->bl1v[j2] : 0.0f;
            #pragma unroll
            for (int k = 0; k < 64; k += 4) {
                float4 a  = *(const float4*)&s->zp[r * 68 + k];
                float4 w1 = *(const float4*)&s->Wl1w[j1 * 64 + k];
                acc1 += a.x * w1.x + a.y * w1.y + a.z * w1.z + a.w * w1.w;
                if (has2) {
                    float4 w2 = *(const float4*)&s->Wl1w[j2 * 64 + k];
                    acc2 += a.x * w2.x + a.y * w2.y + a.z * w2.z + a.w * w2.w;
                }
            }
            s->z1[r * 21 + j1] = fmaxf(acc1, 0.0f);
            if (has2) s->z1[r * 21 + j2] = fmaxf(acc2, 0.0f);
        }
        __syncthreads();

        // S3: z2 = relu(z1 @ Wl2.T + bl2)
        {
            const int  j1   = slot;
            const int  j2   = 16 + slot;
            const bool has2 = (slot < 4);
            float acc1 = s->bl2v[j1];
            float acc2 = has2 ? s->bl2v[j2] : 0.0f;
            #pragma unroll
            for (int k = 0; k < ODIM; ++k) {
                float a = s->z1[r * 21 + k];
                acc1 += a * s->Wl2w[j1 * ODIM + k];
                if (has2) acc2 += a * s->Wl2w[j2 * ODIM + k];
            }
            s->z2[r * 21 + j1] = fmaxf(acc1, 0.0f);
            if (has2) s->z2[r * 21 + j2] = fmaxf(acc2, 0.0f);
        }
        __syncthreads();

        // S4: z3 = z2 @ Wl3.T + bl3 ; z = zp + dt*z3 ; cond-select into h/c
        {
            const int j0 = slot * 4;
            float4 b3 = *(const float4*)&s->bl3v[j0];
            float z3r[4] = {b3.x, b3.y, b3.z, b3.w};
            #pragma unroll
            for (int k = 0; k < ODIM; ++k) {
                float a = s->z2[r * 21 + k];
                float4 w = *(const float4*)&s->Wl3T[k * 64 + j0];
                z3r[0] += a * w.x; z3r[1] += a * w.y;
                z3r[2] += a * w.z; z3r[3] += a * w.w;
            }
            if (cond) {
                #pragma unroll
                for (int i = 0; i < 4; ++i) {
                    float z = zpr[i] + dt * z3r[i];
                    int j = j0 + i;
                    if (j < 32) s->h[r * 33 + j] = z;
                    else        s->c[r * 33 + (j - 32)] = z;
                }
            }
        }
        __syncthreads();

        // S5: gates = bvec + ob@M.T + h_in @ W_hh.T   (128 outputs/row)
        {
            const int j0 = slot * 8;
            const float ob0 = s->ob[r * 8 + 0];
            const float ob1 = s->ob[r * 8 + 1];
            const float ob2 = s->ob[r * 8 + 2];
            const float ob3 = s->ob[r * 8 + 3];
            float acc[8];
            #pragma unroll
            for (int jj = 0; jj < 8; ++jj) {
                acc[jj] = bvec[jj]
                        + ob0 * Mreg[jj][0] + ob1 * Mreg[jj][1]
                        + ob2 * Mreg[jj][2] + ob3 * Mreg[jj][3];
            }
            #pragma unroll
            for (int k = 0; k < 32; ++k) {
                float a = s->h[r * 33 + k];
                float4 w0 = *(const float4*)&s->WhhT[k * 128 + j0];
                float4 w1 = *(const float4*)&s->WhhT[k * 128 + j0 + 4];
                acc[0] += a * w0.x; acc[1] += a * w0.y;
                acc[2] += a * w0.z; acc[3] += a * w0.w;
                acc[4] += a * w1.x; acc[5] += a * w1.y;
                acc[6] += a * w1.z; acc[7] += a * w1.w;
            }
            *(float4*)&s->gate[r * 132 + j0]     = make_float4(acc[0], acc[1], acc[2], acc[3]);
            *(float4*)&s->gate[r * 132 + j0 + 4] = make_float4(acc[4], acc[5], acc[6], acc[7]);
        }
        __syncthreads();

        // S6: LSTM elementwise; update state; write output (2 units per thread)
        {
            const int j = 2 * slot;
            const int gb = r * 132;
            float gi0 = s->gate[gb + j],      gi1 = s->gate[gb + j + 1];
            float gf0 = s->gate[gb + 32 + j], gf1 = s->gate[gb + 32 + j + 1];
            float gg0 = s->gate[gb + 64 + j], gg1 = s->gate[gb + 64 + j + 1];
            float go0 = s->gate[gb + 96 + j], go1 = s->gate[gb + 96 + j + 1];
            float ci0 = s->c[r * 33 + j],     ci1 = s->c[r * 33 + j + 1];

            float cn0 = sigf(gf0) * ci0 + sigf(gi0) * tanh_f(gg0);
            float cn1 = sigf(gf1) * ci1 + sigf(gi1) * tanh_f(gg1);
            float hn0 = sigf(go0) * tanh_f(cn0);
            float hn1 = sigf(go1) * tanh_f(cn1);

            s->c[r * 33 + j]     = cn0;
            s->c[r * 33 + j + 1] = cn1;
            s->h[r * 33 + j]     = hn0;
            s->h[r * 33 + j + 1] = hn1;

            *(float2*)&out[((size_t)(b0 + r) * TT + t) * LDIM + j] = make_float2(hn0, hn1);
        }
        // NOTE: no barrier needed here. Next iteration's S0 only writes s->ob,
        // whose last readers (S5) are fenced by the S5->S6 barrier; next S1's
        // reads of h/c are fenced by the barrier after S0.
    }
}

extern "C" void kernel_launch(void* const* d_in, const int* in_sizes, int n_in,
                              void* d_out, int out_size)
{
    const float* obs  = (const float*)d_in[0];
    const float* h0   = (const float*)d_in[1];
    const float* c0   = (const float*)d_in[2];
    const float* W1   = (const float*)d_in[3];
    const float* b1   = (const float*)d_in[4];
    const float* W_ih = (const float*)d_in[5];
    const float* W_hh = (const float*)d_in[6];
    const float* b_ih = (const float*)d_in[7];
    const float* b_hh = (const float*)d_in[8];
    const float* W_xi = (const float*)d_in[9];
    const float* b_xi = (const float*)d_in[10];
    const float* Wl1  = (const float*)d_in[11];
    const float* bl1  = (const float*)d_in[12];
    const float* Wl2  = (const float*)d_in[13];
    const float* bl2  = (const float*)d_in[14];
    const float* Wl3  = (const float*)d_in[15];
    const float* bl3  = (const float*)d_in[16];
    float* out = (float*)d_out;

    const int smem_bytes = (int)sizeof(Smem);
    cudaFuncSetAttribute(ppo_rnn_kernel,
                         cudaFuncAttributeMaxDynamicSharedMemorySize, smem_bytes);

    ppo_rnn_kernel<<<NCTA, NTH, smem_bytes>>>(
        obs, h0, c0, W1, b1, W_ih, W_hh, b_ih, b_hh,
        W_xi, b_xi, Wl1, bl1, Wl2, bl2, Wl3, bl3, out);
}